// round 1
// baseline (speedup 1.0000x reference)
#include <cuda_runtime.h>

// Problem dims (fixed by the dataset)
#define N_ROWS 32768
#define M_CENT 4096
#define D_DIM  32

#define MSPLIT 4            // split over centers -> 512 CTAs
#define CHUNK  128          // centers per shared-memory tile
#define BLOCK  256          // threads per block (1 n-row per thread)
#define CPS    (M_CENT / MSPLIT)   // centers per split = 1024

// Scratch (no cudaMalloc allowed)
__device__ float g_ysT[D_DIM * M_CENT];   // pre-scaled centers, k-major [32][4096]
__device__ float g_y2t[M_CENT];           // -0.5 * ||y_scaled||^2
__device__ float g_part[MSPLIT * N_ROWS]; // per-split partial sums

typedef unsigned long long ull;

// ---- packed f32x2 helpers (Blackwell) ----
__device__ __forceinline__ ull fma2(ull a, ull b, ull c) {
    ull d; asm("fma.rn.f32x2 %0, %1, %2, %3;" : "=l"(d) : "l"(a), "l"(b), "l"(c)); return d;
}
__device__ __forceinline__ ull add2(ull a, ull b) {
    ull d; asm("add.rn.f32x2 %0, %1, %2;" : "=l"(d) : "l"(a), "l"(b)); return d;
}
__device__ __forceinline__ ull pack2(float lo, float hi) {
    ull d; asm("mov.b64 %0, {%1, %2};" : "=l"(d) : "f"(lo), "f"(hi)); return d;
}
__device__ __forceinline__ void unpack2(ull v, float& lo, float& hi) {
    asm("mov.b64 {%0, %1}, %2;" : "=f"(lo), "=f"(hi) : "l"(v));
}
__device__ __forceinline__ float ex2f(float x) {
    float r; asm("ex2.approx.f32 %0, %1;" : "=f"(r) : "f"(x)); return r;
}

// ---- prep: scale centers by sqrt(log2e)/g, transpose to k-major, compute -0.5||ys||^2 ----
__global__ void prep_kernel(const float* __restrict__ centers,
                            const float* __restrict__ sigma) {
    int m = blockIdx.x * blockDim.x + threadIdx.x;
    if (m >= M_CENT) return;
    float g = sigma[0];
    float s = 1.44269504088896340736f / (g * g);   // log2(e)/g^2
    float c = sqrtf(s);
    float y2 = 0.f;
#pragma unroll
    for (int k = 0; k < D_DIM; k++) {
        float v = centers[m * D_DIM + k] * c;
        g_ysT[k * M_CENT + m] = v;
        y2 += v * v;
    }
    g_y2t[m] = -0.5f * y2;
}

// ---- main: each thread owns one n-row; centers packed 2-per-f32x2 lane ----
__global__ void __launch_bounds__(BLOCK, 2)
rbf_main(const float* __restrict__ X,
         const float* __restrict__ alphas,
         const float* __restrict__ sigma) {
    __shared__ __align__(16) float ysh[D_DIM][CHUNK];  // k-major tile: LDS.128 -> {y_c0,y_c1},{y_c2,y_c3}
    __shared__ __align__(16) float y2sh[CHUNK];
    __shared__ __align__(16) float ash[CHUNK];

    const int n      = blockIdx.x * BLOCK + threadIdx.x;
    const int split  = blockIdx.y;
    const int mbase0 = split * CPS;

    const float g = sigma[0];
    const float c = sqrtf(1.44269504088896340736f / (g * g));

    // Load + scale this thread's X row; pack {x,x} once (reused over all centers).
    ull xv[D_DIM];
    float x2 = 0.f;
    const float4* xp = reinterpret_cast<const float4*>(X + (size_t)n * D_DIM);
#pragma unroll
    for (int q = 0; q < D_DIM / 4; q++) {
        float4 v = xp[q];
        v.x *= c; v.y *= c; v.z *= c; v.w *= c;
        x2 += v.x * v.x + v.y * v.y + v.z * v.z + v.w * v.w;
        xv[4 * q + 0] = pack2(v.x, v.x);
        xv[4 * q + 1] = pack2(v.y, v.y);
        xv[4 * q + 2] = pack2(v.z, v.z);
        xv[4 * q + 3] = pack2(v.w, v.w);
    }
    const ull x2p = pack2(-0.5f * x2, -0.5f * x2);

    ull oacc = pack2(0.f, 0.f);

    for (int ch = 0; ch < CPS / CHUNK; ch++) {
        const int m_base = mbase0 + ch * CHUNK;
        __syncthreads();   // protect previous tile's readers
        // cooperative tile load: 32*128 floats, coalesced
#pragma unroll
        for (int i = 0; i < (D_DIM * CHUNK) / BLOCK; i++) {
            int idx = threadIdx.x + i * BLOCK;
            int k  = idx >> 7;          // /CHUNK
            int cc = idx & (CHUNK - 1); // %CHUNK
            ysh[k][cc] = g_ysT[k * M_CENT + m_base + cc];
        }
        if (threadIdx.x < CHUNK) {
            y2sh[threadIdx.x] = g_y2t[m_base + threadIdx.x];
        } else {
            ash[threadIdx.x - CHUNK] = alphas[m_base + threadIdx.x - CHUNK];
        }
        __syncthreads();

        // 8 centers (4 packed pairs) at a time -> 4 independent FMA chains
        for (int c8 = 0; c8 < CHUNK; c8 += 8) {
            ulonglong2 t01 = *reinterpret_cast<const ulonglong2*>(&y2sh[c8]);
            ulonglong2 t23 = *reinterpret_cast<const ulonglong2*>(&y2sh[c8 + 4]);
            ull acc0 = add2(t01.x, x2p);
            ull acc1 = add2(t01.y, x2p);
            ull acc2 = add2(t23.x, x2p);
            ull acc3 = add2(t23.y, x2p);
#pragma unroll
            for (int k = 0; k < D_DIM; k++) {
                ulonglong2 y01 = *reinterpret_cast<const ulonglong2*>(&ysh[k][c8]);
                ulonglong2 y23 = *reinterpret_cast<const ulonglong2*>(&ysh[k][c8 + 4]);
                acc0 = fma2(xv[k], y01.x, acc0);
                acc1 = fma2(xv[k], y01.y, acc1);
                acc2 = fma2(xv[k], y23.x, acc2);
                acc3 = fma2(xv[k], y23.y, acc3);
            }
            // epilogue: arg <= 0 always, ex2 never overflows
            float e0, e1, e2, e3, e4, e5, e6, e7;
            unpack2(acc0, e0, e1); unpack2(acc1, e2, e3);
            unpack2(acc2, e4, e5); unpack2(acc3, e6, e7);
            e0 = ex2f(e0); e1 = ex2f(e1); e2 = ex2f(e2); e3 = ex2f(e3);
            e4 = ex2f(e4); e5 = ex2f(e5); e6 = ex2f(e6); e7 = ex2f(e7);
            ulonglong2 a01 = *reinterpret_cast<const ulonglong2*>(&ash[c8]);
            ulonglong2 a23 = *reinterpret_cast<const ulonglong2*>(&ash[c8 + 4]);
            oacc = fma2(pack2(e0, e1), a01.x, oacc);
            oacc = fma2(pack2(e2, e3), a01.y, oacc);
            oacc = fma2(pack2(e4, e5), a23.x, oacc);
            oacc = fma2(pack2(e6, e7), a23.y, oacc);
        }
    }

    float o0, o1;
    unpack2(oacc, o0, o1);
    g_part[split * N_ROWS + n] = o0 + o1;
}

// ---- deterministic final reduce over the 4 splits ----
__global__ void reduce_kernel(float* __restrict__ out) {
    int n = blockIdx.x * blockDim.x + threadIdx.x;
    float s = 0.f;
#pragma unroll
    for (int i = 0; i < MSPLIT; i++) s += g_part[i * N_ROWS + n];
    out[n] = s;
}

extern "C" void kernel_launch(void* const* d_in, const int* in_sizes, int n_in,
                              void* d_out, int out_size) {
    const float* X       = (const float*)d_in[0];
    const float* centers = (const float*)d_in[1];
    const float* alphas  = (const float*)d_in[2];
    const float* sigma   = (const float*)d_in[3];
    float* out = (float*)d_out;

    prep_kernel<<<(M_CENT + 255) / 256, 256>>>(centers, sigma);
    dim3 grid(N_ROWS / BLOCK, MSPLIT);
    rbf_main<<<grid, BLOCK>>>(X, alphas, sigma);
    reduce_kernel<<<N_ROWS / 256, 256>>>(out);
}

// round 3
// speedup vs baseline: 2.0020x; 2.0020x over previous
#include <cuda_runtime.h>
#include <cuda_bf16.h>
#include <cstdint>

// ---------------- problem dims ----------------
#define N_ROWS 32768
#define M_CENT 4096
#define D_DIM  32

#define BLOCK     256          // 8 warps
#define ROWS_CTA  128          // rows per CTA (warp = 16 rows)
#define NTILE     128          // centers per SMEM tile
#define NTILES    (M_CENT / NTILE)   // 32
#define KBF       96           // split K in bf16: [hi|lo/hi...]
#define BSTRIDE   208          // padded row stride in bytes (13*16, conflict-free)

// SMEM byte offsets
#define SMEM_A    0
#define SMEM_B0   (ROWS_CTA * BSTRIDE)            // 26624
#define SMEM_B1   (SMEM_B0 + NTILE * BSTRIDE)     // 53248
#define SMEM_YA0  (SMEM_B1 + NTILE * BSTRIDE)     // 79872
#define SMEM_YA1  (SMEM_YA0 + NTILE * 8)          // 80896
#define SMEM_X2   (SMEM_YA1 + NTILE * 8)          // 81920
#define SMEM_TOT  (SMEM_X2 + ROWS_CTA * 4)        // 82432

// ---------------- device scratch ----------------
__device__ __nv_bfloat16 g_B[M_CENT * KBF];   // [m][96]: hi(0-31) | hi(32-63) | lo(64-95)
__device__ float2        g_ya[M_CENT];        // { -0.5*||ys||^2 , alpha }

// ---------------- helpers ----------------
__device__ __forceinline__ uint32_t smem_u32(const void* p) {
    uint32_t a;
    asm("{ .reg .u64 t; cvta.to.shared.u64 t, %1; cvt.u32.u64 %0, t; }" : "=r"(a) : "l"(p));
    return a;
}
__device__ __forceinline__ float ex2f(float x) {
    float r; asm("ex2.approx.f32 %0, %1;" : "=f"(r) : "f"(x)); return r;
}
__device__ __forceinline__ void cp16(uint32_t dst, const void* src) {
    asm volatile("cp.async.cg.shared.global [%0], [%1], 16;" :: "r"(dst), "l"(src));
}
__device__ __forceinline__ void cp_commit() {
    asm volatile("cp.async.commit_group;" ::: "memory");
}
template <int N>
__device__ __forceinline__ void cp_wait() {
    asm volatile("cp.async.wait_group %0;" :: "n"(N) : "memory");
}
__device__ __forceinline__ void ldmatrix_x4(uint32_t& r0, uint32_t& r1, uint32_t& r2, uint32_t& r3,
                                            uint32_t addr) {
    asm volatile("ldmatrix.sync.aligned.m8n8.x4.shared.b16 {%0,%1,%2,%3}, [%4];"
                 : "=r"(r0), "=r"(r1), "=r"(r2), "=r"(r3) : "r"(addr));
}
__device__ __forceinline__ void mma_bf16(float& d0, float& d1, float& d2, float& d3,
                                         uint32_t a0, uint32_t a1, uint32_t a2, uint32_t a3,
                                         uint32_t b0, uint32_t b1) {
    asm volatile(
        "mma.sync.aligned.m16n8k16.row.col.f32.bf16.bf16.f32 "
        "{%0,%1,%2,%3}, {%4,%5,%6,%7}, {%8,%9}, {%0,%1,%2,%3};"
        : "+f"(d0), "+f"(d1), "+f"(d2), "+f"(d3)
        : "r"(a0), "r"(a1), "r"(a2), "r"(a3), "r"(b0), "r"(b1));
}
__device__ __forceinline__ uint32_t pack_bf2(__nv_bfloat16 lo, __nv_bfloat16 hi) {
    __nv_bfloat162 t(lo, hi);
    return *reinterpret_cast<uint32_t*>(&t);
}

// ---------------- prep: split centers to bf16 hi/lo, y2+alpha table ----------------
__global__ void prep_kernel(const float* __restrict__ centers,
                            const float* __restrict__ alphas,
                            const float* __restrict__ sigma) {
    int m = blockIdx.x * blockDim.x + threadIdx.x;
    if (m >= M_CENT) return;
    float g = sigma[0];
    float c = sqrtf(1.44269504088896340736f / (g * g));   // sqrt(log2e)/g
    float y2 = 0.f;
#pragma unroll
    for (int k = 0; k < D_DIM; k++) {
        float v = centers[m * D_DIM + k] * c;
        y2 += v * v;
        __nv_bfloat16 hi = __float2bfloat16(v);
        __nv_bfloat16 lo = __float2bfloat16(v - __bfloat162float(hi));
        g_B[m * KBF + k]      = hi;   // pairs with A-hi
        g_B[m * KBF + 32 + k] = hi;   // pairs with A-lo
        g_B[m * KBF + 64 + k] = lo;   // pairs with A-hi
    }
    g_ya[m] = make_float2(-0.5f * y2, alphas[m]);
}

// ---------------- tile loaders (cp.async) ----------------
__device__ __forceinline__ void load_btile(uint32_t sbase, int buf, int tile, int tid) {
    const char* gsrc = reinterpret_cast<const char*>(g_B) + (size_t)tile * NTILE * (KBF * 2);
    uint32_t bdst = sbase + (buf ? SMEM_B1 : SMEM_B0);
#pragma unroll
    for (int i = 0; i < 6; i++) {
        int idx = tid + i * BLOCK;            // 0..1535 chunks of 16B
        int c = idx / 12, r = idx % 12;       // 12 chunks per center (192B)
        cp16(bdst + c * BSTRIDE + r * 16, gsrc + idx * 16);
    }
    if (tid < 64) {
        const char* ysrc = reinterpret_cast<const char*>(g_ya) + (size_t)tile * NTILE * 8;
        cp16(sbase + (buf ? SMEM_YA1 : SMEM_YA0) + tid * 16, ysrc + tid * 16);
    }
}

// ---------------- main kernel ----------------
__global__ void __launch_bounds__(BLOCK)
rbf_main(const float* __restrict__ X,
         const float* __restrict__ sigma,
         float* __restrict__ out) {
    extern __shared__ char smem[];
    const uint32_t sbase = smem_u32(smem);
    const int tid = threadIdx.x;
    const int w   = tid >> 5;
    const int ln  = tid & 31;

    // kick off tiles 0 and 1 before doing anything else
    load_btile(sbase, 0, 0, tid); cp_commit();
    load_btile(sbase, 1, 1, tid); cp_commit();

    // ---- A staging: rows 0..127, hi/lo split into SMEM; x2 per row ----
    const float g = __ldg(sigma);
    const float c = sqrtf(1.44269504088896340736f / (g * g));
    if (tid < ROWS_CTA) {
        const int gRow = blockIdx.x * ROWS_CTA + tid;
        const float4* xp = reinterpret_cast<const float4*>(X + (size_t)gRow * D_DIM);
        float v[D_DIM]; float x2 = 0.f;
#pragma unroll
        for (int q = 0; q < 8; q++) {
            float4 t = xp[q];
            t.x *= c; t.y *= c; t.z *= c; t.w *= c;
            v[4*q] = t.x; v[4*q+1] = t.y; v[4*q+2] = t.z; v[4*q+3] = t.w;
            x2 += t.x*t.x + t.y*t.y + t.z*t.z + t.w*t.w;
        }
        char* arow = smem + SMEM_A + tid * BSTRIDE;
#pragma unroll
        for (int q = 0; q < 16; q++) {
            float a0 = v[2*q], a1 = v[2*q+1];
            __nv_bfloat16 h0 = __float2bfloat16(a0), h1 = __float2bfloat16(a1);
            __nv_bfloat16 l0 = __float2bfloat16(a0 - __bfloat162float(h0));
            __nv_bfloat16 l1 = __float2bfloat16(a1 - __bfloat162float(h1));
            *reinterpret_cast<uint32_t*>(arow + 4*q)        = pack_bf2(h0, h1);   // cols 0-31 hi
            *reinterpret_cast<uint32_t*>(arow + 64 + 4*q)   = pack_bf2(l0, l1);   // cols 32-63 lo
            *reinterpret_cast<uint32_t*>(arow + 128 + 4*q)  = pack_bf2(h0, h1);   // cols 64-95 hi
        }
        *reinterpret_cast<float*>(smem + SMEM_X2 + tid * 4) = -0.5f * x2;
    }
    __syncthreads();

    // ---- load persistent A fragments (24 regs) + x2 ----
    const int gID  = ln >> 2;              // 0..7
    const int qid  = ln & 3;               // 0..3
    const int row0 = w * 16 + gID;
    const int row1 = row0 + 8;
    uint32_t af[6][4];
    {
        const char* a0p = smem + SMEM_A + row0 * BSTRIDE + qid * 4;
        const char* a1p = smem + SMEM_A + row1 * BSTRIDE + qid * 4;
#pragma unroll
        for (int s = 0; s < 6; s++) {
            af[s][0] = *reinterpret_cast<const uint32_t*>(a0p + s * 32);
            af[s][1] = *reinterpret_cast<const uint32_t*>(a1p + s * 32);
            af[s][2] = *reinterpret_cast<const uint32_t*>(a0p + s * 32 + 16);
            af[s][3] = *reinterpret_cast<const uint32_t*>(a1p + s * 32 + 16);
        }
    }
    const float x2r0 = *reinterpret_cast<const float*>(smem + SMEM_X2 + row0 * 4);
    const float x2r1 = *reinterpret_cast<const float*>(smem + SMEM_X2 + row1 * 4);

    // ldmatrix per-lane base offset within a B tile
    const uint32_t blane = (uint32_t)((ln & 7) * BSTRIDE + (ln >> 3) * 16);

    cp_wait<1>();            // tile 0 resident
    __syncthreads();

    float acc0 = 0.f, acc1 = 0.f;

    for (int t = 0; t < NTILES; t++) {
        const int buf = t & 1;
        const uint32_t Bb  = sbase + (buf ? SMEM_B1 : SMEM_B0) + blane;
        const char*    yab = smem + (buf ? SMEM_YA1 : SMEM_YA0);

#pragma unroll 4
        for (int gi = 0; gi < NTILE / 8; gi++) {
            const uint32_t gb = Bb + gi * (8 * BSTRIDE);
            float dA0 = 0.f, dA1 = 0.f, dA2 = 0.f, dA3 = 0.f;
            float dB0 = 0.f, dB1 = 0.f, dB2 = 0.f, dB3 = 0.f;
            uint32_t p0, p1, p2, p3, q0, q1, q2, q3, r0, r1, r2, r3;
            ldmatrix_x4(p0, p1, p2, p3, gb);          // ksteps 0,1 (hi*hi)
            ldmatrix_x4(q0, q1, q2, q3, gb + 64);     // ksteps 2,3 (lo*hi)
            ldmatrix_x4(r0, r1, r2, r3, gb + 128);    // ksteps 4,5 (hi*hi, hi*lo)
            mma_bf16(dA0, dA1, dA2, dA3, af[0][0], af[0][1], af[0][2], af[0][3], p0, p1);
            mma_bf16(dB0, dB1, dB2, dB3, af[2][0], af[2][1], af[2][2], af[2][3], q0, q1);
            mma_bf16(dA0, dA1, dA2, dA3, af[1][0], af[1][1], af[1][2], af[1][3], p2, p3);
            mma_bf16(dB0, dB1, dB2, dB3, af[3][0], af[3][1], af[3][2], af[3][3], q2, q3);
            mma_bf16(dA0, dA1, dA2, dA3, af[4][0], af[4][1], af[4][2], af[4][3], r0, r1);
            mma_bf16(dB0, dB1, dB2, dB3, af[5][0], af[5][1], af[5][2], af[5][3], r2, r3);

            // epilogue: cols n0 = gi*8 + 2*qid (+1)
            float4 ya = *reinterpret_cast<const float4*>(yab + gi * 64 + qid * 16);
            float t00 = ya.x + x2r0, t10 = ya.z + x2r0;
            float t01 = ya.x + x2r1, t11 = ya.z + x2r1;
            acc0 = fmaf(ex2f(dA0 + dB0 + t00), ya.y, acc0);
            acc0 = fmaf(ex2f(dA1 + dB1 + t10), ya.w, acc0);
            acc1 = fmaf(ex2f(dA2 + dB2 + t01), ya.y, acc1);
            acc1 = fmaf(ex2f(dA3 + dB3 + t11), ya.w, acc1);
        }

        __syncthreads();                       // everyone done reading buf
        if (t + 2 < NTILES) {
            load_btile(sbase, buf, t + 2, tid);
            cp_commit();
            cp_wait<1>();                      // tile t+1 resident
        } else {
            cp_wait<0>();
        }
        __syncthreads();
    }

    // reduce across the 4 lanes sharing each row
    acc0 += __shfl_xor_sync(0xFFFFFFFFu, acc0, 1);
    acc0 += __shfl_xor_sync(0xFFFFFFFFu, acc0, 2);
    acc1 += __shfl_xor_sync(0xFFFFFFFFu, acc1, 1);
    acc1 += __shfl_xor_sync(0xFFFFFFFFu, acc1, 2);
    if (qid == 0) {
        const int base = blockIdx.x * ROWS_CTA;
        out[base + row0] = acc0;
        out[base + row1] = acc1;
    }
}

// ---------------- launch ----------------
extern "C" void kernel_launch(void* const* d_in, const int* in_sizes, int n_in,
                              void* d_out, int out_size) {
    const float* X       = (const float*)d_in[0];
    const float* centers = (const float*)d_in[1];
    const float* alphas  = (const float*)d_in[2];
    const float* sigma   = (const float*)d_in[3];
    float* out = (float*)d_out;

    cudaFuncSetAttribute(rbf_main, cudaFuncAttributeMaxDynamicSharedMemorySize, SMEM_TOT);

    prep_kernel<<<M_CENT / 256, 256>>>(centers, alphas, sigma);
    rbf_main<<<N_ROWS / ROWS_CTA, BLOCK, SMEM_TOT>>>(X, sigma, out);
}

// round 4
// speedup vs baseline: 2.8825x; 1.4398x over previous
#include <cuda_runtime.h>
#include <cuda_bf16.h>
#include <cstdint>

// ---------------- problem dims ----------------
#define N_ROWS 32768
#define M_CENT 4096
#define D_DIM  32

#define BLOCK     256                    // 8 warps, warp = 16 rows
#define ROWS_CTA  128
#define NTILE     128                    // centers per SMEM tile
#define MSPLIT    2                      // split centers across CTAs
#define CPS       (M_CENT / MSPLIT)      // 2048 centers per CTA
#define TILES     (CPS / NTILE)          // 16
#define BSTRIDE   144                    // 128B payload + 16B pad (odd*16 -> LDSM conflict-free)

// SMEM byte offsets (single static block, 39.4KB -> 3 CTAs/SM)
#define SMEM_B0   0
#define SMEM_B1   (NTILE * BSTRIDE)              // 18432
#define SMEM_YA0  (2 * NTILE * BSTRIDE)          // 36864
#define SMEM_YA1  (SMEM_YA0 + NTILE * 8)         // 37888
#define SMEM_X2   (SMEM_YA1 + NTILE * 8)         // 38912
#define SMEM_TOT  (SMEM_X2 + ROWS_CTA * 4)       // 39424

// ---------------- device scratch ----------------
__device__ __nv_bfloat16 g_B[M_CENT * 64];   // [m][ hi(32) | lo(32) ]
__device__ float2        g_ya[M_CENT];       // { -0.5*||ys||^2 , alpha }
__device__ float         g_part[MSPLIT * N_ROWS];

// ---------------- helpers ----------------
__device__ __forceinline__ uint32_t smem_u32(const void* p) {
    uint32_t a;
    asm("{ .reg .u64 t; cvta.to.shared.u64 t, %1; cvt.u32.u64 %0, t; }" : "=r"(a) : "l"(p));
    return a;
}
__device__ __forceinline__ float ex2f(float x) {
    float r; asm("ex2.approx.f32 %0, %1;" : "=f"(r) : "f"(x)); return r;
}
__device__ __forceinline__ void cp16(uint32_t dst, const void* src) {
    asm volatile("cp.async.cg.shared.global [%0], [%1], 16;" :: "r"(dst), "l"(src));
}
__device__ __forceinline__ void cp_commit() {
    asm volatile("cp.async.commit_group;" ::: "memory");
}
template <int N>
__device__ __forceinline__ void cp_wait() {
    asm volatile("cp.async.wait_group %0;" :: "n"(N) : "memory");
}
__device__ __forceinline__ void ldmx4(uint32_t* r, uint32_t addr) {
    asm volatile("ldmatrix.sync.aligned.m8n8.x4.shared.b16 {%0,%1,%2,%3}, [%4];"
                 : "=r"(r[0]), "=r"(r[1]), "=r"(r[2]), "=r"(r[3]) : "r"(addr));
}
__device__ __forceinline__ void mma_bf16(float& d0, float& d1, float& d2, float& d3,
                                         uint32_t a0, uint32_t a1, uint32_t a2, uint32_t a3,
                                         uint32_t b0, uint32_t b1) {
    asm volatile(
        "mma.sync.aligned.m16n8k16.row.col.f32.bf16.bf16.f32 "
        "{%0,%1,%2,%3}, {%4,%5,%6,%7}, {%8,%9}, {%0,%1,%2,%3};"
        : "+f"(d0), "+f"(d1), "+f"(d2), "+f"(d3)
        : "r"(a0), "r"(a1), "r"(a2), "r"(a3), "r"(b0), "r"(b1));
}
__device__ __forceinline__ uint32_t pack_bf2(__nv_bfloat16 lo, __nv_bfloat16 hi) {
    __nv_bfloat162 t(lo, hi);
    return *reinterpret_cast<uint32_t*>(&t);
}

// ---------------- prep: warp per center, coalesced ----------------
__global__ void prep_kernel(const float* __restrict__ centers,
                            const float* __restrict__ alphas,
                            const float* __restrict__ sigma) {
    const int m  = (blockIdx.x * blockDim.x + threadIdx.x) >> 5;
    const int ln = threadIdx.x & 31;
    if (m >= M_CENT) return;
    const float g = sigma[0];
    const float c = sqrtf(1.44269504088896340736f / (g * g));   // sqrt(log2e)/g
    float v = centers[m * D_DIM + ln] * c;
    __nv_bfloat16 hi = __float2bfloat16(v);
    __nv_bfloat16 lo = __float2bfloat16(v - __bfloat162float(hi));
    g_B[m * 64 + ln]      = hi;
    g_B[m * 64 + 32 + ln] = lo;
    float y2 = v * v;
#pragma unroll
    for (int o = 16; o; o >>= 1) y2 += __shfl_xor_sync(0xFFFFFFFFu, y2, o);
    if (ln == 0) g_ya[m] = make_float2(-0.5f * y2, alphas[m]);
}

// ---------------- B tile loader (cp.async) ----------------
__device__ __forceinline__ void load_btile(uint32_t sb, int buf, int split, int t, int tid) {
    const char* src = reinterpret_cast<const char*>(g_B) +
                      ((size_t)split * CPS + (size_t)t * NTILE) * 128;
    const uint32_t bd = sb + (buf ? SMEM_B1 : SMEM_B0);
#pragma unroll
    for (int i = 0; i < 4; i++) {
        int idx = tid + i * BLOCK;        // 0..1023 chunks of 16B (8 per center)
        int cc = idx >> 3, rr = idx & 7;
        cp16(bd + cc * BSTRIDE + rr * 16, src + idx * 16);
    }
    if (tid < 64) {
        const char* ys = reinterpret_cast<const char*>(g_ya + split * CPS + t * NTILE);
        cp16(sb + (buf ? SMEM_YA1 : SMEM_YA0) + tid * 16, ys + tid * 16);
    }
}

// ---------------- main kernel ----------------
__global__ void __launch_bounds__(BLOCK, 3)
rbf_main(const float* __restrict__ X,
         const float* __restrict__ sigma) {
    __shared__ __align__(128) char smem[SMEM_TOT];
    const uint32_t sb = smem_u32(smem);
    const int tid = threadIdx.x;
    const int w   = tid >> 5;
    const int ln  = tid & 31;
    const int split = blockIdx.y;

    // ---- A staging into B0 region (consumed before pipeline starts) ----
    const float g = __ldg(sigma);
    const float c = sqrtf(1.44269504088896340736f / (g * g));
    if (tid < ROWS_CTA) {
        const int gRow = blockIdx.x * ROWS_CTA + tid;
        const float4* xp = reinterpret_cast<const float4*>(X + (size_t)gRow * D_DIM);
        float v[D_DIM]; float x2 = 0.f;
#pragma unroll
        for (int q = 0; q < 8; q++) {
            float4 t = xp[q];
            t.x *= c; t.y *= c; t.z *= c; t.w *= c;
            v[4*q] = t.x; v[4*q+1] = t.y; v[4*q+2] = t.z; v[4*q+3] = t.w;
            x2 += t.x*t.x + t.y*t.y + t.z*t.z + t.w*t.w;
        }
        char* arow = smem + tid * BSTRIDE;
#pragma unroll
        for (int q = 0; q < 16; q++) {
            float a0 = v[2*q], a1 = v[2*q+1];
            __nv_bfloat16 h0 = __float2bfloat16(a0), h1 = __float2bfloat16(a1);
            __nv_bfloat16 l0 = __float2bfloat16(a0 - __bfloat162float(h0));
            __nv_bfloat16 l1 = __float2bfloat16(a1 - __bfloat162float(h1));
            *reinterpret_cast<uint32_t*>(arow + 4*q)      = pack_bf2(h0, h1);  // hi: bytes 0-63
            *reinterpret_cast<uint32_t*>(arow + 64 + 4*q) = pack_bf2(l0, l1);  // lo: bytes 64-127
        }
        *reinterpret_cast<float*>(smem + SMEM_X2 + tid * 4) = -0.5f * x2;
    }
    __syncthreads();

    // ---- persistent A fragments: 4 ksteps (hi k0-15, hi k16-31, lo k0-15, lo k16-31) ----
    const int gID  = ln >> 2;
    const int qid  = ln & 3;
    const int row0 = w * 16 + gID;
    const int row1 = row0 + 8;
    uint32_t af[4][4];
    {
        const char* a0p = smem + row0 * BSTRIDE + qid * 4;
        const char* a1p = smem + row1 * BSTRIDE + qid * 4;
#pragma unroll
        for (int s = 0; s < 4; s++) {
            af[s][0] = *reinterpret_cast<const uint32_t*>(a0p + s * 32);
            af[s][1] = *reinterpret_cast<const uint32_t*>(a1p + s * 32);
            af[s][2] = *reinterpret_cast<const uint32_t*>(a0p + s * 32 + 16);
            af[s][3] = *reinterpret_cast<const uint32_t*>(a1p + s * 32 + 16);
        }
    }
    const float x2r0 = *reinterpret_cast<const float*>(smem + SMEM_X2 + row0 * 4);
    const float x2r1 = *reinterpret_cast<const float*>(smem + SMEM_X2 + row1 * 4);
    __syncthreads();   // A stage region free -> cp.async may overwrite

    // ---- pipeline prologue: tiles 0,1 ----
    load_btile(sb, 0, split, 0, tid); cp_commit();
    load_btile(sb, 1, split, 1, tid); cp_commit();
    cp_wait<1>();
    __syncthreads();

    const uint32_t blane = (uint32_t)((ln & 7) * BSTRIDE + (ln >> 3) * 16);
    float acc0 = 0.f, acc1 = 0.f;

    for (int t = 0; t < TILES; t++) {
        const int buf = t & 1;
        const uint32_t Bb  = sb + (buf ? SMEM_B1 : SMEM_B0) + blane;
        const char*    yab = smem + (buf ? SMEM_YA1 : SMEM_YA0);

        uint32_t p[4], r[4], pn[4], rn[4];
        ldmx4(p, Bb);            // hi k0-31 of group 0
        ldmx4(r, Bb + 64);       // lo k0-31 of group 0

#pragma unroll
        for (int gi = 0; gi < NTILE / 8; gi++) {
            if (gi + 1 < NTILE / 8) {                 // prefetch next group's fragments
                const uint32_t nb = Bb + (gi + 1) * (8 * BSTRIDE);
                ldmx4(pn, nb);
                ldmx4(rn, nb + 64);
            }
            float dA0=0.f,dA1=0.f,dA2=0.f,dA3=0.f;
            float dB0=0.f,dB1=0.f,dB2=0.f,dB3=0.f;
            // x.y ~= xh*yh + xl*yh + xh*yl   (K_eff = 96)
            mma_bf16(dA0,dA1,dA2,dA3, af[0][0],af[0][1],af[0][2],af[0][3], p[0],p[1]); // hi*hi k0-15
            mma_bf16(dB0,dB1,dB2,dB3, af[2][0],af[2][1],af[2][2],af[2][3], p[0],p[1]); // lo*hi k0-15
            mma_bf16(dA0,dA1,dA2,dA3, af[1][0],af[1][1],af[1][2],af[1][3], p[2],p[3]); // hi*hi k16-31
            mma_bf16(dB0,dB1,dB2,dB3, af[3][0],af[3][1],af[3][2],af[3][3], p[2],p[3]); // lo*hi k16-31
            mma_bf16(dA0,dA1,dA2,dA3, af[0][0],af[0][1],af[0][2],af[0][3], r[0],r[1]); // hi*lo k0-15
            mma_bf16(dB0,dB1,dB2,dB3, af[1][0],af[1][1],af[1][2],af[1][3], r[2],r[3]); // hi*lo k16-31

            float4 ya = *reinterpret_cast<const float4*>(yab + gi * 64 + qid * 16);
            acc0 = fmaf(ex2f(dA0 + dB0 + ya.x + x2r0), ya.y, acc0);
            acc0 = fmaf(ex2f(dA1 + dB1 + ya.z + x2r0), ya.w, acc0);
            acc1 = fmaf(ex2f(dA2 + dB2 + ya.x + x2r1), ya.y, acc1);
            acc1 = fmaf(ex2f(dA3 + dB3 + ya.z + x2r1), ya.w, acc1);
#pragma unroll
            for (int i = 0; i < 4; i++) { p[i] = pn[i]; r[i] = rn[i]; }
        }

        __syncthreads();                   // all warps done reading buf
        if (t + 2 < TILES) {
            load_btile(sb, buf, split, t + 2, tid);
            cp_commit();
            cp_wait<1>();                  // tile t+1 resident
        } else {
            cp_wait<0>();
        }
        __syncthreads();
    }

    // reduce across the 4 lanes sharing each row
    acc0 += __shfl_xor_sync(0xFFFFFFFFu, acc0, 1);
    acc0 += __shfl_xor_sync(0xFFFFFFFFu, acc0, 2);
    acc1 += __shfl_xor_sync(0xFFFFFFFFu, acc1, 1);
    acc1 += __shfl_xor_sync(0xFFFFFFFFu, acc1, 2);
    if (qid == 0) {
        float* dst = g_part + (size_t)split * N_ROWS + blockIdx.x * ROWS_CTA;
        dst[row0] = acc0;
        dst[row1] = acc1;
    }
}

// ---------------- final reduce over splits ----------------
__global__ void reduce_kernel(float* __restrict__ out) {
    int n = blockIdx.x * blockDim.x + threadIdx.x;
    out[n] = g_part[n] + g_part[N_ROWS + n];
}

// ---------------- launch ----------------
extern "C" void kernel_launch(void* const* d_in, const int* in_sizes, int n_in,
                              void* d_out, int out_size) {
    const float* X       = (const float*)d_in[0];
    const float* centers = (const float*)d_in[1];
    const float* alphas  = (const float*)d_in[2];
    const float* sigma   = (const float*)d_in[3];
    float* out = (float*)d_out;

    prep_kernel<<<M_CENT / 8, 256>>>(centers, alphas, sigma);   // 8 centers per 256-thr block
    dim3 grid(N_ROWS / ROWS_CTA, MSPLIT);                       // 256 x 2 = 512 CTAs
    rbf_main<<<grid, BLOCK>>>(X, sigma);
    reduce_kernel<<<N_ROWS / 256, 256>>>(out);
}

// round 5
// speedup vs baseline: 3.3519x; 1.1629x over previous
#include <cuda_runtime.h>
#include <cuda_bf16.h>
#include <cstdint>

// ---------------- problem dims ----------------
#define N_ROWS 32768
#define M_CENT 4096
#define D_DIM  32

#define BLOCK     256                    // 8 warps, warp = 16 rows
#define ROWS_CTA  128
#define NTILE     128                    // centers per tile (= one split)
#define NSPLIT    32                     // center splits
#define NRB       (N_ROWS / ROWS_CTA)    // 256 row blocks
#define TOTTILES  (NRB * NSPLIT)         // 8192 work tiles
#define NCTAS     444                    // 148 SMs x 3 CTAs -> single wave
#define BSTRIDE   144                    // 128B payload + 16B pad (conflict-free LDSM)

#define SLOT_B    (NTILE * BSTRIDE)      // 18432
#define SLOT_YA   (NTILE * 8)            // 1024
#define SLOT      (SLOT_B + SLOT_YA)     // 19456
#define SMEM_TOT  (3 * SLOT)             // 58368 (dynamic)

// ---------------- device scratch ----------------
__device__ __nv_bfloat16 g_B[M_CENT * 64];       // [m][ hi(32) | lo(32) ]
__device__ float2        g_ya[M_CENT];           // { -0.5*||ys||^2 , alpha }
__device__ float         g_part[NSPLIT * N_ROWS];// 4MB partials

// ---------------- helpers ----------------
__device__ __forceinline__ uint32_t smem_u32(const void* p) {
    uint32_t a;
    asm("{ .reg .u64 t; cvta.to.shared.u64 t, %1; cvt.u32.u64 %0, t; }" : "=r"(a) : "l"(p));
    return a;
}
__device__ __forceinline__ float ex2f(float x) {
    float r; asm("ex2.approx.f32 %0, %1;" : "=f"(r) : "f"(x)); return r;
}
__device__ __forceinline__ void cp16(uint32_t dst, const void* src) {
    asm volatile("cp.async.cg.shared.global [%0], [%1], 16;" :: "r"(dst), "l"(src));
}
__device__ __forceinline__ void cp_commit() {
    asm volatile("cp.async.commit_group;" ::: "memory");
}
template <int N>
__device__ __forceinline__ void cp_wait() {
    asm volatile("cp.async.wait_group %0;" :: "n"(N) : "memory");
}
__device__ __forceinline__ void ldmx4(uint32_t* r, uint32_t addr) {
    asm volatile("ldmatrix.sync.aligned.m8n8.x4.shared.b16 {%0,%1,%2,%3}, [%4];"
                 : "=r"(r[0]), "=r"(r[1]), "=r"(r[2]), "=r"(r[3]) : "r"(addr));
}
__device__ __forceinline__ void mma_bf16(float& d0, float& d1, float& d2, float& d3,
                                         uint32_t a0, uint32_t a1, uint32_t a2, uint32_t a3,
                                         uint32_t b0, uint32_t b1) {
    asm volatile(
        "mma.sync.aligned.m16n8k16.row.col.f32.bf16.bf16.f32 "
        "{%0,%1,%2,%3}, {%4,%5,%6,%7}, {%8,%9}, {%0,%1,%2,%3};"
        : "+f"(d0), "+f"(d1), "+f"(d2), "+f"(d3)
        : "r"(a0), "r"(a1), "r"(a2), "r"(a3), "r"(b0), "r"(b1));
}
__device__ __forceinline__ uint32_t pack_bf2(float a0, float a1) {
    __nv_bfloat162 t(__float2bfloat16(a0), __float2bfloat16(a1));
    return *reinterpret_cast<uint32_t*>(&t);
}

// ---------------- prep: warp per center ----------------
__global__ void prep_kernel(const float* __restrict__ centers,
                            const float* __restrict__ alphas,
                            const float* __restrict__ sigma) {
    const int m  = (blockIdx.x * blockDim.x + threadIdx.x) >> 5;
    const int ln = threadIdx.x & 31;
    if (m >= M_CENT) return;
    const float g = sigma[0];
    const float c = sqrtf(1.44269504088896340736f / (g * g));   // sqrt(log2e)/g
    float v = centers[m * D_DIM + ln] * c;
    __nv_bfloat16 hi = __float2bfloat16(v);
    __nv_bfloat16 lo = __float2bfloat16(v - __bfloat162float(hi));
    g_B[m * 64 + ln]      = hi;
    g_B[m * 64 + 32 + ln] = lo;
    float y2 = v * v;
#pragma unroll
    for (int o = 16; o; o >>= 1) y2 += __shfl_xor_sync(0xFFFFFFFFu, y2, o);
    if (ln == 0) g_ya[m] = make_float2(-0.5f * y2, alphas[m]);
}

// ---------------- B tile loader: tile T -> ring slot ----------------
__device__ __forceinline__ void load_btile(uint32_t sb, int slot, int T, int tid) {
    const int split = T & (NSPLIT - 1);
    const char* src = reinterpret_cast<const char*>(g_B) + (size_t)split * NTILE * 128;
    const uint32_t bd = sb + slot * SLOT;
#pragma unroll
    for (int i = 0; i < 4; i++) {
        int idx = tid + i * BLOCK;          // 0..1023 16B chunks (8 per center)
        int cc = idx >> 3, rr = idx & 7;
        cp16(bd + cc * BSTRIDE + rr * 16, src + idx * 16);
    }
    if (tid < 64) {
        const char* ys = reinterpret_cast<const char*>(g_ya + split * NTILE);
        cp16(bd + SLOT_B + tid * 16, ys + tid * 16);
    }
}

// ---------------- main kernel: persistent balanced tiles ----------------
__global__ void __launch_bounds__(BLOCK, 3)
rbf_main(const float* __restrict__ X,
         const float* __restrict__ sigma) {
    extern __shared__ char smem[];
    const uint32_t sb = smem_u32(smem);
    const int tid  = threadIdx.x;
    const int w    = tid >> 5;
    const int ln   = tid & 31;
    const int gID  = ln >> 2;
    const int qid  = ln & 3;
    const int row0 = w * 16 + gID;      // CTA-local rows
    const int row1 = row0 + 8;

    const float g = __ldg(sigma);
    const float c = sqrtf(1.44269504088896340736f / (g * g));

    // contiguous balanced chunk of tiles
    const int cta = blockIdx.x;
    const int loT = (int)(((long long)cta * TOTTILES) / NCTAS);
    const int hiT = (int)(((long long)(cta + 1) * TOTTILES) / NCTAS);
    const int n   = hiT - loT;

    // prologue: tiles loT, loT+1 (uniform group counting: always commit)
    load_btile(sb, 0, loT, tid);
    cp_commit();
    if (n > 1) load_btile(sb, 1, loT + 1, tid);
    cp_commit();

    const uint32_t blane = (uint32_t)((ln & 7) * BSTRIDE + (ln >> 3) * 16);

    uint32_t af[4][4];
    float ex0 = 1.f, ex1 = 1.f;
    int curRb = -1;

    for (int i = 0; i < n; i++) {
        const int T  = loT + i;
        const int rb = T >> 5;

        cp_wait<1>();          // tile i resident
        __syncthreads();       // visible to all; slot (i+2)%3 free
        if (i + 2 < n) load_btile(sb, (i + 2) % 3, T + 2, tid);
        cp_commit();

        // ---- A fragments straight from global X (registers only) ----
        if (rb != curRb) {
            curRb = rb;
            const float* r0p = X + ((size_t)rb * ROWS_CTA + row0) * D_DIM + qid * 2;
            const float* r1p = X + ((size_t)rb * ROWS_CTA + row1) * D_DIM + qid * 2;
            float s0 = 0.f, s1 = 0.f;
#pragma unroll
            for (int j = 0; j < 4; j++) {                 // cols 2qid + 8j
                float2 v0 = *reinterpret_cast<const float2*>(r0p + j * 8);
                float2 v1 = *reinterpret_cast<const float2*>(r1p + j * 8);
                v0.x *= c; v0.y *= c; v1.x *= c; v1.y *= c;
                s0 += v0.x * v0.x + v0.y * v0.y;
                s1 += v1.x * v1.x + v1.y * v1.y;
                const int s = j >> 1;                     // kstep (hi)
                const int h = (j & 1) << 1;               // 0 or 2 within frag
                // hi fragments
                float h0x = __bfloat162float(__float2bfloat16(v0.x));
                float h0y = __bfloat162float(__float2bfloat16(v0.y));
                float h1x = __bfloat162float(__float2bfloat16(v1.x));
                float h1y = __bfloat162float(__float2bfloat16(v1.y));
                af[s][h + 0] = pack_bf2(v0.x, v0.y);
                af[s][h + 1] = pack_bf2(v1.x, v1.y);
                // lo fragments
                af[2 + s][h + 0] = pack_bf2(v0.x - h0x, v0.y - h0y);
                af[2 + s][h + 1] = pack_bf2(v1.x - h1x, v1.y - h1y);
            }
            // quad reduce -> full ||x||^2 per row; fold exp(-x2/2) out of the sum
            s0 += __shfl_xor_sync(0xFFFFFFFFu, s0, 1);
            s0 += __shfl_xor_sync(0xFFFFFFFFu, s0, 2);
            s1 += __shfl_xor_sync(0xFFFFFFFFu, s1, 1);
            s1 += __shfl_xor_sync(0xFFFFFFFFu, s1, 2);
            ex0 = ex2f(-0.5f * s0);
            ex1 = ex2f(-0.5f * s1);
        }

        // ---- consume tile ----
        const uint32_t Bb  = sb + (i % 3) * SLOT + blane;
        const char*    yab = smem + (i % 3) * SLOT + SLOT_B;

        float acc0 = 0.f, acc1 = 0.f;
        uint32_t p[4], r[4], pn[4], rn[4];
        ldmx4(p, Bb);          // hi k0-31, group 0
        ldmx4(r, Bb + 64);     // lo k0-31, group 0

#pragma unroll
        for (int gi = 0; gi < NTILE / 8; gi++) {
            if (gi + 1 < NTILE / 8) {
                const uint32_t nb = Bb + (gi + 1) * (8 * BSTRIDE);
                ldmx4(pn, nb);
                ldmx4(rn, nb + 64);
            }
            float dA0=0.f,dA1=0.f,dA2=0.f,dA3=0.f;
            float dB0=0.f,dB1=0.f,dB2=0.f,dB3=0.f;
            // x.y ~= xh*yh + xl*yh + xh*yl   (K_eff = 96)
            mma_bf16(dA0,dA1,dA2,dA3, af[0][0],af[0][1],af[0][2],af[0][3], p[0],p[1]);
            mma_bf16(dB0,dB1,dB2,dB3, af[2][0],af[2][1],af[2][2],af[2][3], p[0],p[1]);
            mma_bf16(dA0,dA1,dA2,dA3, af[1][0],af[1][1],af[1][2],af[1][3], p[2],p[3]);
            mma_bf16(dB0,dB1,dB2,dB3, af[3][0],af[3][1],af[3][2],af[3][3], p[2],p[3]);
            mma_bf16(dA0,dA1,dA2,dA3, af[0][0],af[0][1],af[0][2],af[0][3], r[0],r[1]);
            mma_bf16(dB0,dB1,dB2,dB3, af[1][0],af[1][1],af[1][2],af[1][3], r[2],r[3]);

            float4 ya = *reinterpret_cast<const float4*>(yab + gi * 64 + qid * 16);
            acc0 = fmaf(ex2f(dA0 + dB0 + ya.x), ya.y, acc0);
            acc0 = fmaf(ex2f(dA1 + dB1 + ya.z), ya.w, acc0);
            acc1 = fmaf(ex2f(dA2 + dB2 + ya.x), ya.y, acc1);
            acc1 = fmaf(ex2f(dA3 + dB3 + ya.z), ya.w, acc1);
#pragma unroll
            for (int k = 0; k < 4; k++) { p[k] = pn[k]; r[k] = rn[k]; }
        }

        // quad reduce + store partial for this (split, rb)
        acc0 += __shfl_xor_sync(0xFFFFFFFFu, acc0, 1);
        acc0 += __shfl_xor_sync(0xFFFFFFFFu, acc0, 2);
        acc1 += __shfl_xor_sync(0xFFFFFFFFu, acc1, 1);
        acc1 += __shfl_xor_sync(0xFFFFFFFFu, acc1, 2);
        if (qid == 0) {
            float* dst = g_part + (size_t)(T & (NSPLIT - 1)) * N_ROWS + rb * ROWS_CTA;
            dst[row0] = acc0 * ex0;
            dst[row1] = acc1 * ex1;
        }
    }
}

// ---------------- final reduce over 32 splits ----------------
__global__ void reduce_kernel(float* __restrict__ out) {
    const int nidx = blockIdx.x * blockDim.x + threadIdx.x;
    float s = 0.f;
#pragma unroll
    for (int i = 0; i < NSPLIT; i++) s += g_part[(size_t)i * N_ROWS + nidx];
    out[nidx] = s;
}

// ---------------- launch ----------------
extern "C" void kernel_launch(void* const* d_in, const int* in_sizes, int n_in,
                              void* d_out, int out_size) {
    const float* X       = (const float*)d_in[0];
    const float* centers = (const float*)d_in[1];
    const float* alphas  = (const float*)d_in[2];
    const float* sigma   = (const float*)d_in[3];
    float* out = (float*)d_out;

    cudaFuncSetAttribute(rbf_main, cudaFuncAttributeMaxDynamicSharedMemorySize, SMEM_TOT);

    prep_kernel<<<M_CENT / 8, 256>>>(centers, alphas, sigma);
    rbf_main<<<NCTAS, BLOCK, SMEM_TOT>>>(X, sigma);
    reduce_kernel<<<N_ROWS / 256, 256>>>(out);
}

// round 6
// speedup vs baseline: 3.3946x; 1.0127x over previous
#include <cuda_runtime.h>
#include <cuda_bf16.h>
#include <cstdint>

// ---------------- problem dims ----------------
#define N_ROWS 32768
#define M_CENT 4096
#define D_DIM  32

#define BLOCK     256                    // 8 warps, warp = 16 rows
#define ROWS_CTA  128
#define NTILE     128                    // centers per tile (= one split)
#define NSPLIT    32                     // center splits
#define NRB       (N_ROWS / ROWS_CTA)    // 256 row blocks
#define TOTTILES  (NRB * NSPLIT)         // 8192 work tiles
#define NCTAS     592                    // 148 SMs x 4 CTAs -> single wave
#define BSTRIDE   144                    // 128B payload + 16B pad (conflict-free LDSM)

#define SLOT_B    (NTILE * BSTRIDE)      // 18432
#define SLOT_YA   (NTILE * 8)            // 1024
#define SLOT      (SLOT_B + SLOT_YA)     // 19456
#define SMEM_TOT  (2 * SLOT)             // 38912 -> 4 CTAs/SM

// ---------------- device scratch ----------------
__device__ __nv_bfloat16 g_B[M_CENT * 64];        // [m][ hi(32) | lo(32) ]
__device__ float2        g_ya[M_CENT];            // { -0.5*||ys||^2 , alpha }
__device__ float         g_part[NSPLIT * N_ROWS]; // partials

// ---------------- helpers ----------------
__device__ __forceinline__ uint32_t smem_u32(const void* p) {
    uint32_t a;
    asm("{ .reg .u64 t; cvta.to.shared.u64 t, %1; cvt.u32.u64 %0, t; }" : "=r"(a) : "l"(p));
    return a;
}
__device__ __forceinline__ float ex2f(float x) {
    float r; asm("ex2.approx.f32 %0, %1;" : "=f"(r) : "f"(x)); return r;
}
__device__ __forceinline__ void cp16(uint32_t dst, const void* src) {
    asm volatile("cp.async.cg.shared.global [%0], [%1], 16;" :: "r"(dst), "l"(src));
}
__device__ __forceinline__ void cp_commit() {
    asm volatile("cp.async.commit_group;" ::: "memory");
}
template <int N>
__device__ __forceinline__ void cp_wait() {
    asm volatile("cp.async.wait_group %0;" :: "n"(N) : "memory");
}
__device__ __forceinline__ void ldmx4(uint32_t* r, uint32_t addr) {
    asm volatile("ldmatrix.sync.aligned.m8n8.x4.shared.b16 {%0,%1,%2,%3}, [%4];"
                 : "=r"(r[0]), "=r"(r[1]), "=r"(r[2]), "=r"(r[3]) : "r"(addr));
}
__device__ __forceinline__ void mma_bf16(float& d0, float& d1, float& d2, float& d3,
                                         uint32_t a0, uint32_t a1, uint32_t a2, uint32_t a3,
                                         uint32_t b0, uint32_t b1) {
    asm volatile(
        "mma.sync.aligned.m16n8k16.row.col.f32.bf16.bf16.f32 "
        "{%0,%1,%2,%3}, {%4,%5,%6,%7}, {%8,%9}, {%0,%1,%2,%3};"
        : "+f"(d0), "+f"(d1), "+f"(d2), "+f"(d3)
        : "r"(a0), "r"(a1), "r"(a2), "r"(a3), "r"(b0), "r"(b1));
}
__device__ __forceinline__ uint32_t pack_bf2(float a0, float a1) {
    __nv_bfloat162 t(__float2bfloat16(a0), __float2bfloat16(a1));
    return *reinterpret_cast<uint32_t*>(&t);
}

// ---------------- prep: warp per center ----------------
__global__ void prep_kernel(const float* __restrict__ centers,
                            const float* __restrict__ alphas,
                            const float* __restrict__ sigma) {
    const int m  = (blockIdx.x * blockDim.x + threadIdx.x) >> 5;
    const int ln = threadIdx.x & 31;
    if (m >= M_CENT) return;
    const float g = sigma[0];
    const float c = sqrtf(1.44269504088896340736f / (g * g));   // sqrt(log2e)/g
    float v = centers[m * D_DIM + ln] * c;
    __nv_bfloat16 hi = __float2bfloat16(v);
    __nv_bfloat16 lo = __float2bfloat16(v - __bfloat162float(hi));
    g_B[m * 64 + ln]      = hi;
    g_B[m * 64 + 32 + ln] = lo;
    float y2 = v * v;
#pragma unroll
    for (int o = 16; o; o >>= 1) y2 += __shfl_xor_sync(0xFFFFFFFFu, y2, o);
    if (ln == 0) g_ya[m] = make_float2(-0.5f * y2, alphas[m]);
}

// ---------------- B tile loader: tile T -> ring slot ----------------
__device__ __forceinline__ void load_btile(uint32_t sb, int slot, int T, int tid) {
    const int split = T & (NSPLIT - 1);
    const char* src = reinterpret_cast<const char*>(g_B) + (size_t)split * NTILE * 128;
    const uint32_t bd = sb + slot * SLOT;
#pragma unroll
    for (int i = 0; i < 4; i++) {
        int idx = tid + i * BLOCK;          // 0..1023 16B chunks (8 per center)
        int cc = idx >> 3, rr = idx & 7;
        cp16(bd + cc * BSTRIDE + rr * 16, src + idx * 16);
    }
    if (tid < 64) {
        const char* ys = reinterpret_cast<const char*>(g_ya + split * NTILE);
        cp16(bd + SLOT_B + tid * 16, ys + tid * 16);
    }
}

// ---------------- main kernel: persistent, 4 CTAs/SM ----------------
__global__ void __launch_bounds__(BLOCK, 4)
rbf_main(const float* __restrict__ X,
         const float* __restrict__ sigma) {
    extern __shared__ char smem[];
    const uint32_t sb = smem_u32(smem);
    const int tid  = threadIdx.x;
    const int w    = tid >> 5;
    const int ln   = tid & 31;
    const int gID  = ln >> 2;
    const int qid  = ln & 3;
    const int row0 = w * 16 + gID;      // CTA-local rows
    const int row1 = row0 + 8;

    const float g = __ldg(sigma);
    const float c = sqrtf(1.44269504088896340736f / (g * g));

    // contiguous balanced chunk of tiles
    const int cta = blockIdx.x;
    const int loT = (int)(((long long)cta * TOTTILES) / NCTAS);
    const int hiT = (int)(((long long)(cta + 1) * TOTTILES) / NCTAS);
    const int n   = hiT - loT;

    // prologue: tiles loT, loT+1 into slots 0,1
    load_btile(sb, 0, loT, tid);
    cp_commit();
    if (n > 1) load_btile(sb, 1, loT + 1, tid);
    cp_commit();

    const uint32_t blane = (uint32_t)((ln & 7) * BSTRIDE + (ln >> 3) * 16);

    uint32_t af[4][4];
    float ex0 = 1.f, ex1 = 1.f;
    int curRb = -1;

    for (int i = 0; i < n; i++) {
        const int T  = loT + i;
        const int rb = T >> 5;

        cp_wait<1>();          // tile i resident (my groups)
        __syncthreads();       // collective visibility

        // ---- A fragments straight from global X (registers only) ----
        if (rb != curRb) {
            curRb = rb;
            const float* r0p = X + ((size_t)rb * ROWS_CTA + row0) * D_DIM + qid * 2;
            const float* r1p = X + ((size_t)rb * ROWS_CTA + row1) * D_DIM + qid * 2;
            float s0 = 0.f, s1 = 0.f;
#pragma unroll
            for (int j = 0; j < 4; j++) {                 // cols 2qid + 8j
                float2 v0 = *reinterpret_cast<const float2*>(r0p + j * 8);
                float2 v1 = *reinterpret_cast<const float2*>(r1p + j * 8);
                v0.x *= c; v0.y *= c; v1.x *= c; v1.y *= c;
                s0 += v0.x * v0.x + v0.y * v0.y;
                s1 += v1.x * v1.x + v1.y * v1.y;
                const int s = j >> 1;                     // kstep
                const int h = (j & 1) << 1;
                float h0x = __bfloat162float(__float2bfloat16(v0.x));
                float h0y = __bfloat162float(__float2bfloat16(v0.y));
                float h1x = __bfloat162float(__float2bfloat16(v1.x));
                float h1y = __bfloat162float(__float2bfloat16(v1.y));
                af[s][h + 0] = pack_bf2(v0.x, v0.y);
                af[s][h + 1] = pack_bf2(v1.x, v1.y);
                af[2 + s][h + 0] = pack_bf2(v0.x - h0x, v0.y - h0y);
                af[2 + s][h + 1] = pack_bf2(v1.x - h1x, v1.y - h1y);
            }
            s0 += __shfl_xor_sync(0xFFFFFFFFu, s0, 1);
            s0 += __shfl_xor_sync(0xFFFFFFFFu, s0, 2);
            s1 += __shfl_xor_sync(0xFFFFFFFFu, s1, 1);
            s1 += __shfl_xor_sync(0xFFFFFFFFu, s1, 2);
            ex0 = ex2f(-0.5f * s0);
            ex1 = ex2f(-0.5f * s1);
        }

        // ---- consume tile i from slot i&1 ----
        const uint32_t Bb  = sb + (i & 1) * SLOT + blane;
        const char*    yab = smem + (i & 1) * SLOT + SLOT_B;

        float acc0 = 0.f, acc1 = 0.f;
#pragma unroll
        for (int gi = 0; gi < NTILE / 8; gi++) {
            const uint32_t gb = Bb + gi * (8 * BSTRIDE);
            uint32_t p[4], r[4];
            ldmx4(p, gb);          // hi k0-31
            ldmx4(r, gb + 64);     // lo k0-31

            float dA0=0.f,dA1=0.f,dA2=0.f,dA3=0.f;
            float dB0=0.f,dB1=0.f,dB2=0.f,dB3=0.f;
            // x.y ~= xh*yh + xl*yh + xh*yl   (K_eff = 96)
            mma_bf16(dA0,dA1,dA2,dA3, af[0][0],af[0][1],af[0][2],af[0][3], p[0],p[1]);
            mma_bf16(dB0,dB1,dB2,dB3, af[2][0],af[2][1],af[2][2],af[2][3], p[0],p[1]);
            mma_bf16(dA0,dA1,dA2,dA3, af[1][0],af[1][1],af[1][2],af[1][3], p[2],p[3]);
            mma_bf16(dB0,dB1,dB2,dB3, af[3][0],af[3][1],af[3][2],af[3][3], p[2],p[3]);
            mma_bf16(dA0,dA1,dA2,dA3, af[0][0],af[0][1],af[0][2],af[0][3], r[0],r[1]);
            mma_bf16(dB0,dB1,dB2,dB3, af[1][0],af[1][1],af[1][2],af[1][3], r[2],r[3]);

            float4 ya = *reinterpret_cast<const float4*>(yab + gi * 64 + qid * 16);
            acc0 = fmaf(ex2f(dA0 + dB0 + ya.x), ya.y, acc0);
            acc0 = fmaf(ex2f(dA1 + dB1 + ya.z), ya.w, acc0);
            acc1 = fmaf(ex2f(dA2 + dB2 + ya.x), ya.y, acc1);
            acc1 = fmaf(ex2f(dA3 + dB3 + ya.z), ya.w, acc1);
        }

        __syncthreads();                   // all warps done reading slot i&1
        if (i + 2 < n) load_btile(sb, i & 1, T + 2, tid);
        cp_commit();                       // uniform group counting

        // quad reduce + store partial for this (split, rb)
        acc0 += __shfl_xor_sync(0xFFFFFFFFu, acc0, 1);
        acc0 += __shfl_xor_sync(0xFFFFFFFFu, acc0, 2);
        acc1 += __shfl_xor_sync(0xFFFFFFFFu, acc1, 1);
        acc1 += __shfl_xor_sync(0xFFFFFFFFu, acc1, 2);
        if (qid == 0) {
            float* dst = g_part + (size_t)(T & (NSPLIT - 1)) * N_ROWS + rb * ROWS_CTA;
            dst[row0] = acc0 * ex0;
            dst[row1] = acc1 * ex1;
        }
    }
}

// ---------------- final reduce over 32 splits ----------------
__global__ void reduce_kernel(float* __restrict__ out) {
    const int nidx = blockIdx.x * blockDim.x + threadIdx.x;
    float s = 0.f;
#pragma unroll
    for (int i = 0; i < NSPLIT; i++) s += g_part[(size_t)i * N_ROWS + nidx];
    out[nidx] = s;
}

// ---------------- launch ----------------
extern "C" void kernel_launch(void* const* d_in, const int* in_sizes, int n_in,
                              void* d_out, int out_size) {
    const float* X       = (const float*)d_in[0];
    const float* centers = (const float*)d_in[1];
    const float* alphas  = (const float*)d_in[2];
    const float* sigma   = (const float*)d_in[3];
    float* out = (float*)d_out;

    cudaFuncSetAttribute(rbf_main, cudaFuncAttributeMaxDynamicSharedMemorySize, SMEM_TOT);

    prep_kernel<<<M_CENT / 8, 256>>>(centers, alphas, sigma);
    rbf_main<<<NCTAS, BLOCK, SMEM_TOT>>>(X, sigma);
    reduce_kernel<<<N_ROWS / 256, 256>>>(out);
}